// round 10
// baseline (speedup 1.0000x reference)
#include <cuda_runtime.h>
#include <math.h>

// B,H,L,D = 4,8,2048,64 ; FACTOR=5 -> sample_k = n_top = 40
#define Bq    4
#define Hq    8
#define Lq    2048
#define Dq    64
#define BH    (Bq*Hq)
#define SK    40
#define NT    40
#define NP    4            // K slices for k_M2
#define SL    (Lq/NP)      // 512 rows per slice
#define ZSP   4            // l-splits per (p,bh) in k_M2
#define ZL    (Lq/ZSP)     // 512 queries per z
#define LMAX  (ZL*SK)      // staged list worst case
#define NCH   64           // cumsum chunks
#define CHLEN (Lq/NCH)     // 32
#define NJT   8            // j-tiles (of 256) for fused score+AV
#define JT    (Lq/NJT)     // 256
#define SMEM_M2  (SL*Dq*4 + (ZL+1+3)*4 + LMAX*4)
#define SMEM_SAV (JT*65*4 + NT*16*16 + NT*JT*4 + NT*4 + NT*4 + 64)

// ---- device scratch (no allocations allowed) ----
__device__ int    g_cnt[NP][Lq];
__device__ int    g_off[NP][Lq+1];
__device__ int    g_list[Lq*SK];
__device__ float2 g_part2[NP*BH*Lq];
__device__ int    g_top[BH*NT];
__device__ int    g_sel[BH*Lq];
__device__ float  g_den[BH*NT];
__device__ float  g_part[BH*NJT*NT*Dq];
__device__ float  g_csum[BH*NCH*Dq];

// ---------------------------------------------------------------------------
// Prep 1: per-query per-slice counts; zero g_den; init g_sel = -1.
// ---------------------------------------------------------------------------
__global__ void k_cnt(const int* __restrict__ I) {
    int l = blockIdx.x*256 + threadIdx.x;          // grid 8 -> 2048 threads
    if (l < BH*NT) g_den[l] = 0.f;
    for (int i = 0; i < BH*Lq/2048; ++i) g_sel[i*2048 + l] = -1;
    int c0=0,c1=0,c2=0,c3=0;
    const int* r = I + l*SK;
    #pragma unroll
    for (int s = 0; s < SK; ++s) {
        int p = r[s] >> 9;
        c0 += (p==0); c1 += (p==1); c2 += (p==2); c3 += (p==3);
    }
    g_cnt[0][l]=c0; g_cnt[1][l]=c1; g_cnt[2][l]=c2; g_cnt[3][l]=c3;
}

// Prep 2: exclusive prefix -> global offsets (single block, warp-parallel scan)
__global__ void k_scan() {
    __shared__ int wsum[8];
    __shared__ int s_tot;
    int tid = threadIdx.x, lane = tid & 31, wid = tid >> 5;
    int base = 0;
    for (int p = 0; p < NP; ++p) {
        int loc[8]; int s = 0;
        #pragma unroll
        for (int k = 0; k < 8; ++k) { loc[k] = s; s += g_cnt[p][tid*8+k]; }
        int v = s;
        #pragma unroll
        for (int o = 1; o < 32; o <<= 1) {
            int t = __shfl_up_sync(0xffffffffu, v, o);
            if (lane >= o) v += t;
        }
        if (lane == 31) wsum[wid] = v;
        __syncthreads();
        if (tid == 0) {
            int a = 0;
            #pragma unroll
            for (int i = 0; i < 8; ++i) { int t = wsum[i]; wsum[i] = a; a += t; }
            s_tot = a;
        }
        __syncthreads();
        int excl = v - s + wsum[wid];
        #pragma unroll
        for (int k = 0; k < 8; ++k) g_off[p][tid*8+k] = base + excl + loc[k];
        if (tid == 255) g_off[p][Lq] = base + excl + s;
        base += s_tot;
        __syncthreads();
    }
}

// Prep 3: fill lists (local row index within slice)
__global__ void k_fill(const int* __restrict__ I) {
    int l = blockIdx.x*256 + threadIdx.x;
    int o0=g_off[0][l], o1=g_off[1][l], o2=g_off[2][l], o3=g_off[3][l];
    const int* r = I + l*SK;
    #pragma unroll
    for (int s = 0; s < SK; ++s) {
        int j = r[s];
        int p = j >> 9, jj = j & (SL-1);
        if      (p==0) g_list[o0++] = jj;
        else if (p==1) g_list[o1++] = jj;
        else if (p==2) g_list[o2++] = jj;
        else           g_list[o3++] = jj;
    }
}

// ---------------------------------------------------------------------------
// k_M2 (R7 config, best measured): slice p, bh, z. K slice (512x64, 128KB) +
// list segment + offsets staged in smem. Warp per query pair, 8-lane dot
// groups, 3 shfl per group-dot.
// ---------------------------------------------------------------------------
__global__ void __launch_bounds__(1024) k_M2(const float* __restrict__ Q,
                                             const float* __restrict__ K) {
    extern __shared__ float ks[];
    float4* ks4 = (float4*)ks;
    int* so = (int*)(ks + SL*Dq);
    int* sl = so + (ZL+1+3);
    int p = blockIdx.x, bh = blockIdx.y, z = blockIdx.z;
    int tid = threadIdx.x, warp = tid >> 5, lane = tid & 31;
    int g = lane >> 3, e = lane & 7;
    int zl0 = z*ZL;

    const float4* Ks = (const float4*)(K + ((size_t)bh*Lq + (size_t)p*SL)*Dq);
    for (int i = tid; i < SL*(Dq/4); i += 1024) ks4[i] = Ks[i];

    int sbeg = g_off[p][zl0];
    int send = g_off[p][zl0 + ZL];
    for (int i = tid; i <= ZL; i += 1024) so[i] = g_off[p][zl0 + i] - sbeg;
    for (int i = tid; i < send - sbeg; i += 1024) sl[i] = g_list[sbeg + i];
    __syncthreads();

    const float4* Q4 = (const float4*)Q;
    int l0 = zl0 + warp;
    #pragma unroll 1
    for (int i = 0; i < 16; i += 2) {
        int la = l0 + 32*i, lb = la + 32;
        int lla = warp + 32*i, llb = lla + 32;
        int a0 = so[lla], a1 = so[lla+1];
        int b0 = so[llb], b1 = so[llb+1];
        size_t qra = ((size_t)bh*Lq + la)*16;
        size_t qrb = ((size_t)bh*Lq + lb)*16;
        float4 qa0 = Q4[qra + e], qa1 = Q4[qra + e + 8];
        float4 qb0 = Q4[qrb + e], qb1 = Q4[qrb + e + 8];
        float mx0 = -INFINITY, sm0 = 0.f, mx1 = -INFINITY, sm1 = 0.f;
        int c0 = a0, c1 = b0;
        while (c0 < a1 || c1 < b1) {
            float pr0 = 0.f, pr1 = 0.f;
            bool v0 = false, v1 = false;
            if (c0 < a1) {
                int idx = c0 + g; v0 = idx < a1;
                int j = sl[v0 ? idx : a0];
                const float4* kb = ks4 + (j << 4);
                float4 x = kb[e], y = kb[e + 8];
                pr0 = qa0.x*x.x + qa0.y*x.y + qa0.z*x.z + qa0.w*x.w
                    + qa1.x*y.x + qa1.y*y.y + qa1.z*y.z + qa1.w*y.w;
            }
            if (c1 < b1) {
                int idx = c1 + g; v1 = idx < b1;
                int j = sl[v1 ? idx : b0];
                const float4* kb = ks4 + (j << 4);
                float4 x = kb[e], y = kb[e + 8];
                pr1 = qb0.x*x.x + qb0.y*x.y + qb0.z*x.z + qb0.w*x.w
                    + qb1.x*y.x + qb1.y*y.y + qb1.z*y.z + qb1.w*y.w;
            }
            pr0 += __shfl_xor_sync(0xffffffffu, pr0, 1);
            pr1 += __shfl_xor_sync(0xffffffffu, pr1, 1);
            pr0 += __shfl_xor_sync(0xffffffffu, pr0, 2);
            pr1 += __shfl_xor_sync(0xffffffffu, pr1, 2);
            pr0 += __shfl_xor_sync(0xffffffffu, pr0, 4);
            pr1 += __shfl_xor_sync(0xffffffffu, pr1, 4);
            if (v0) { mx0 = fmaxf(mx0, pr0); sm0 += pr0; }
            if (v1) { mx1 = fmaxf(mx1, pr1); sm1 += pr1; }
            c0 += 4; c1 += 4;
        }
        mx0 = fmaxf(mx0, __shfl_xor_sync(0xffffffffu, mx0, 8));
        mx0 = fmaxf(mx0, __shfl_xor_sync(0xffffffffu, mx0, 16));
        sm0 += __shfl_xor_sync(0xffffffffu, sm0, 8);
        sm0 += __shfl_xor_sync(0xffffffffu, sm0, 16);
        mx1 = fmaxf(mx1, __shfl_xor_sync(0xffffffffu, mx1, 8));
        mx1 = fmaxf(mx1, __shfl_xor_sync(0xffffffffu, mx1, 16));
        sm1 += __shfl_xor_sync(0xffffffffu, sm1, 8);
        sm1 += __shfl_xor_sync(0xffffffffu, sm1, 16);
        if (lane == 0) {
            g_part2[((size_t)p*BH + bh)*Lq + la] = make_float2(mx0, sm0);
            g_part2[((size_t)p*BH + bh)*Lq + lb] = make_float2(mx1, sm1);
        }
    }
}

// ---------------------------------------------------------------------------
// k_topk: radix-select top-40 (exact threshold, lowest-index tie-break).
// ---------------------------------------------------------------------------
__global__ void k_topk() {
    int bh = blockIdx.x, tid = threadIdx.x;
    __shared__ unsigned keys[Lq];
    __shared__ int hist[256];
    __shared__ int tie[Lq];
    __shared__ int tops[NT];
    __shared__ int s_d, s_acc, s_ngt, s_ntie;

    for (int i = tid; i < Lq; i += 256) {
        float mx = -INFINITY, sm = 0.f;
        #pragma unroll
        for (int p = 0; p < NP; ++p) {
            float2 v = g_part2[((size_t)p*BH + bh)*Lq + i];
            mx = fmaxf(mx, v.x); sm += v.y;
        }
        float m = mx - sm * (1.0f/(float)Lq);
        unsigned u = __float_as_uint(m);
        keys[i] = (u & 0x80000000u) ? ~u : (u | 0x80000000u);
    }
    if (tid == 0) { s_ngt = 0; s_ntie = 0; }
    __syncthreads();

    unsigned prefix = 0; int k = NT;
    #pragma unroll
    for (int level = 3; level >= 0; --level) {
        int sh = level*8;
        hist[tid] = 0;
        __syncthreads();
        unsigned maskAbove = (level==3) ? 0u : (0xFFFFFFFFu << (sh+8));
        for (int i = tid; i < Lq; i += 256) {
            unsigned key = keys[i];
            if ((key & maskAbove) == prefix)
                atomicAdd(&hist[(key >> sh) & 255], 1);
        }
        __syncthreads();
        if (tid == 0) {
            int acc = 0, d = 255;
            for (; d > 0; --d) { if (acc + hist[d] >= k) break; acc += hist[d]; }
            s_d = d; s_acc = acc;
        }
        __syncthreads();
        k -= s_acc;
        prefix |= ((unsigned)s_d) << sh;
        __syncthreads();
    }
    unsigned T = prefix;

    for (int i = tid; i < Lq; i += 256) {
        unsigned key = keys[i];
        if (key > T)       { int pos = atomicAdd(&s_ngt, 1);  tops[pos] = i; }
        else if (key == T) { int pos = atomicAdd(&s_ntie, 1); tie[pos]  = i; }
    }
    __syncthreads();
    int ngt = s_ngt, ntie = s_ntie;
    if (tid < 32) {
        for (int t = 0; t < k; ++t) {
            long long best = 0x7FFFFFFFFFFFFFFFLL;
            for (int i = tid; i < ntie; i += 32) {
                long long c = ((long long)tie[i] << 32) | (unsigned)i;
                if (c < best) best = c;
            }
            #pragma unroll
            for (int o = 16; o; o >>= 1) {
                long long c = __shfl_xor_sync(0xffffffffu, best, o);
                if (c < best) best = c;
            }
            if (tid == 0) {
                int slot = (int)(best & 0xffffffffu);
                tops[ngt + t] = (int)(best >> 32);
                tie[slot] = 0x7FFFFFFF;
            }
            __syncwarp();
        }
    }
    __syncthreads();

    if (tid < NT) {
        g_top[bh*NT + tid] = tops[tid];
        g_sel[bh*Lq + tops[tid]] = tid;
    }
}

// ---------------------------------------------------------------------------
// k_sav: FUSED score+exp+AV per (j-tile 256, bh). 256 threads.
// Phase A: thread-per-j computes 40 u dots -> exp -> smem P (causal tile skip),
//          denominators via warp shfl + smem/global atomics.
// Phase B: AV from smem P + gmem V -> g_part partials.
// ---------------------------------------------------------------------------
__global__ void __launch_bounds__(256) k_sav(const float* __restrict__ Q,
                                             const float* __restrict__ K,
                                             const float* __restrict__ V) {
    extern __shared__ char sm_raw[];
    float*  kt   = (float*)sm_raw;                         // JT*65 floats
    float4* qs4  = (float4*)(sm_raw + JT*65*4);            // NT*16 float4
    float*  P    = (float*)(sm_raw + JT*65*4 + NT*16*16);  // NT*JT floats
    int*    mtop = (int*)  (sm_raw + JT*65*4 + NT*16*16 + NT*JT*4);
    float*  dsum = (float*)(sm_raw + JT*65*4 + NT*16*16 + NT*JT*4 + NT*4);

    int jtx = blockIdx.x, bh = blockIdx.y;
    int jt0 = jtx * JT;
    int tid = threadIdx.x, lane = tid & 31;
    int j = tid;                                           // 0..255

    if (tid < NT) { mtop[tid] = g_top[bh*NT + tid]; dsum[tid] = 0.f; }
    __syncthreads();

    const float4* Q4 = (const float4*)Q;
    for (int i = tid; i < NT*16; i += 256) {
        int u = i >> 4, d4 = i & 15;
        qs4[i] = Q4[((size_t)bh*Lq + mtop[u])*16 + d4];
    }
    const float4* K4 = (const float4*)K;
    for (int i = tid; i < JT*16; i += 256) {
        int r = i >> 4, c4 = i & 15;
        float4 v = K4[((size_t)bh*Lq + jt0 + r)*16 + c4];
        kt[r*65 + c4*4+0] = v.x; kt[r*65 + c4*4+1] = v.y;
        kt[r*65 + c4*4+2] = v.z; kt[r*65 + c4*4+3] = v.w;
    }
    __syncthreads();

    // ---- Phase A: scores -> exp -> P ----
    float kr[Dq];
    #pragma unroll
    for (int d = 0; d < Dq; ++d) kr[d] = kt[j*65 + d];

    int jg = jt0 + j;
    #pragma unroll 1
    for (int u = 0; u < NT; ++u) {
        int m = mtop[u];
        if (jt0 > m) { P[u*JT + j] = 0.f; continue; }      // block-uniform skip
        float s = 0.f;
        #pragma unroll
        for (int d4 = 0; d4 < 16; ++d4) {
            float4 qv = qs4[u*16 + d4];
            s += kr[d4*4+0]*qv.x + kr[d4*4+1]*qv.y + kr[d4*4+2]*qv.z + kr[d4*4+3]*qv.w;
        }
        float e = (jg > m) ? 0.f : __expf(s * 0.125f);
        P[u*JT + j] = e;
        float v = e;
        v += __shfl_xor_sync(0xffffffffu, v, 1);
        v += __shfl_xor_sync(0xffffffffu, v, 2);
        v += __shfl_xor_sync(0xffffffffu, v, 4);
        v += __shfl_xor_sync(0xffffffffu, v, 8);
        v += __shfl_xor_sync(0xffffffffu, v, 16);
        if (lane == 0) atomicAdd(&dsum[u], v);
    }
    __syncthreads();
    if (tid < NT) atomicAdd(&g_den[bh*NT + tid], dsum[tid]);

    // ---- Phase B: AV partials ----
    int d = tid & 63, ug = tid >> 6;                       // 4 groups x 10 u
    const float4* P4 = (const float4*)P;                   // row stride 64 f4
    const float* Vb = V + ((size_t)bh*Lq + jt0)*Dq + d;
    float acc[10];
    #pragma unroll
    for (int k = 0; k < 10; ++k) acc[k] = 0.f;

    #pragma unroll 1
    for (int j4 = 0; j4 < 64; ++j4) {
        float v0 = Vb[(size_t)(j4*4+0)*Dq], v1 = Vb[(size_t)(j4*4+1)*Dq];
        float v2 = Vb[(size_t)(j4*4+2)*Dq], v3 = Vb[(size_t)(j4*4+3)*Dq];
        #pragma unroll
        for (int k = 0; k < 10; ++k) {
            float4 pv = P4[(ug*10 + k)*64 + j4];
            acc[k] += pv.x*v0 + pv.y*v1 + pv.z*v2 + pv.w*v3;
        }
    }
    #pragma unroll
    for (int k = 0; k < 10; ++k)
        g_part[(((size_t)bh*NJT + jtx)*NT + ug*10 + k)*Dq + d] = acc[k];
}

// ---------------------------------------------------------------------------
// cumsum: chunk sums, then fused (prefix + scan + combine + scatter).
// ---------------------------------------------------------------------------
__global__ void k_csum1(const float* __restrict__ V) {
    int bh = blockIdx.y;
    int ch = blockIdx.x*4 + (threadIdx.x >> 6);
    int d  = threadIdx.x & 63;
    const float* v = V + ((size_t)bh*Lq + ch*CHLEN)*Dq + d;
    float a = 0.f;
    #pragma unroll
    for (int l = 0; l < CHLEN; l += 4) {
        float x0 = v[(size_t)l*Dq],     x1 = v[(size_t)(l+1)*Dq];
        float x2 = v[(size_t)(l+2)*Dq], x3 = v[(size_t)(l+3)*Dq];
        a += (x0+x1) + (x2+x3);
    }
    g_csum[(bh*NCH + ch)*Dq + d] = a;
}

__global__ void k_csum23(const float* __restrict__ V, float* __restrict__ O) {
    int bh = blockIdx.y;
    int ch = blockIdx.x*4 + (threadIdx.x >> 6);
    int d  = threadIdx.x & 63;

    float a = 0.f;                       // exclusive prefix over chunks < ch
    int c = 0;
    for (; c + 4 <= ch; c += 4) {
        float x0 = g_csum[(bh*NCH + c+0)*Dq + d];
        float x1 = g_csum[(bh*NCH + c+1)*Dq + d];
        float x2 = g_csum[(bh*NCH + c+2)*Dq + d];
        float x3 = g_csum[(bh*NCH + c+3)*Dq + d];
        a += (x0+x1) + (x2+x3);
    }
    for (; c < ch; ++c) a += g_csum[(bh*NCH + c)*Dq + d];

    int l0 = ch*CHLEN;
    size_t base = ((size_t)bh*Lq + l0)*Dq + d;
    const int* sel = g_sel + bh*Lq + l0;
    #pragma unroll 4
    for (int l = 0; l < CHLEN; ++l) {
        a += V[base + (size_t)l*Dq];
        float out = a;
        int s = sel[l];
        if (s >= 0) {
            float acc8 = 0.f;
            #pragma unroll
            for (int js = 0; js < NJT; ++js)
                acc8 += g_part[(((size_t)bh*NJT + js)*NT + s)*Dq + d];
            out = acc8 / g_den[bh*NT + s];
        }
        O[base + (size_t)l*Dq] = out;
    }
}

extern "C" void kernel_launch(void* const* d_in, const int* in_sizes, int n_in,
                              void* d_out, int out_size) {
    const float* Q = (const float*)d_in[0];
    const float* K = (const float*)d_in[1];
    const float* V = (const float*)d_in[2];
    const int*   I = (const int*)  d_in[3];
    float* O = (float*)d_out;

    cudaFuncSetAttribute(k_M2,  cudaFuncAttributeMaxDynamicSharedMemorySize, SMEM_M2);
    cudaFuncSetAttribute(k_sav, cudaFuncAttributeMaxDynamicSharedMemorySize, SMEM_SAV);

    k_cnt   <<<Lq/256, 256>>>(I);
    k_scan  <<<1, 256>>>();
    k_fill  <<<Lq/256, 256>>>(I);
    k_M2    <<<dim3(NP, BH, ZSP), 1024, SMEM_M2>>>(Q, K);
    k_topk  <<<BH, 256>>>();
    k_sav   <<<dim3(NJT, BH), 256, SMEM_SAV>>>(Q, K, V);
    k_csum1 <<<dim3(NCH/4, BH), 256>>>(V);
    k_csum23<<<dim3(NCH/4, BH), 256>>>(V, O);
}

// round 11
// speedup vs baseline: 1.1828x; 1.1828x over previous
#include <cuda_runtime.h>
#include <math.h>

// B,H,L,D = 4,8,2048,64 ; FACTOR=5 -> sample_k = n_top = 40
#define Bq    4
#define Hq    8
#define Lq    2048
#define Dq    64
#define BH    (Bq*Hq)
#define SK    40
#define NT    40
#define NP    4            // K slices for k_M2
#define SL    (Lq/NP)      // 512 rows per slice
#define ZSP   4            // l-splits per (p,bh) in k_M2
#define ZL    (Lq/ZSP)     // 512 queries per z
#define LMAX  (ZL*SK)      // staged list worst case
#define NCH   64           // cumsum chunks
#define CHLEN (Lq/NCH)     // 32
#define NJT   16           // j-tiles (of 128) for fused score+AV
#define JT    (Lq/NJT)     // 128
#define SMEM_M2  (SL*Dq*4 + (ZL+1+3)*4 + LMAX*4)
#define SMEM_SAV (JT*65*4 + NT*16*16 + NT*JT*4 + NT*4 + NT*4 + 64)

// ---- device scratch (no allocations allowed) ----
__device__ int    g_cnt[NP][Lq];
__device__ int    g_off[NP][Lq+1];
__device__ int    g_list[Lq*SK];
__device__ float2 g_part2[NP*BH*Lq];
__device__ int    g_top[BH*NT];
__device__ int    g_sel[BH*Lq];
__device__ float  g_den[BH*NT];
__device__ float  g_part[BH*NJT*NT*Dq];
__device__ float  g_csum[BH*NCH*Dq];

// ---------------------------------------------------------------------------
// Prep 1: per-query per-slice counts; zero g_den; init g_sel = -1.
// ---------------------------------------------------------------------------
__global__ void k_cnt(const int* __restrict__ I) {
    int l = blockIdx.x*256 + threadIdx.x;          // grid 8 -> 2048 threads
    if (l < BH*NT) g_den[l] = 0.f;
    for (int i = 0; i < BH*Lq/2048; ++i) g_sel[i*2048 + l] = -1;
    int c0=0,c1=0,c2=0,c3=0;
    const int* r = I + l*SK;
    #pragma unroll
    for (int s = 0; s < SK; ++s) {
        int p = r[s] >> 9;
        c0 += (p==0); c1 += (p==1); c2 += (p==2); c3 += (p==3);
    }
    g_cnt[0][l]=c0; g_cnt[1][l]=c1; g_cnt[2][l]=c2; g_cnt[3][l]=c3;
}

// Prep 2: exclusive prefix -> global offsets (single block, warp-parallel scan)
__global__ void k_scan() {
    __shared__ int wsum[8];
    __shared__ int s_tot;
    int tid = threadIdx.x, lane = tid & 31, wid = tid >> 5;
    int base = 0;
    for (int p = 0; p < NP; ++p) {
        int loc[8]; int s = 0;
        #pragma unroll
        for (int k = 0; k < 8; ++k) { loc[k] = s; s += g_cnt[p][tid*8+k]; }
        int v = s;
        #pragma unroll
        for (int o = 1; o < 32; o <<= 1) {
            int t = __shfl_up_sync(0xffffffffu, v, o);
            if (lane >= o) v += t;
        }
        if (lane == 31) wsum[wid] = v;
        __syncthreads();
        if (tid == 0) {
            int a = 0;
            #pragma unroll
            for (int i = 0; i < 8; ++i) { int t = wsum[i]; wsum[i] = a; a += t; }
            s_tot = a;
        }
        __syncthreads();
        int excl = v - s + wsum[wid];
        #pragma unroll
        for (int k = 0; k < 8; ++k) g_off[p][tid*8+k] = base + excl + loc[k];
        if (tid == 255) g_off[p][Lq] = base + excl + s;
        base += s_tot;
        __syncthreads();
    }
}

// Prep 3: fill lists (local row index within slice)
__global__ void k_fill(const int* __restrict__ I) {
    int l = blockIdx.x*256 + threadIdx.x;
    int o0=g_off[0][l], o1=g_off[1][l], o2=g_off[2][l], o3=g_off[3][l];
    const int* r = I + l*SK;
    #pragma unroll
    for (int s = 0; s < SK; ++s) {
        int j = r[s];
        int p = j >> 9, jj = j & (SL-1);
        if      (p==0) g_list[o0++] = jj;
        else if (p==1) g_list[o1++] = jj;
        else if (p==2) g_list[o2++] = jj;
        else           g_list[o3++] = jj;
    }
}

// ---------------------------------------------------------------------------
// k_M2 (R7 config, best measured 74us): slice p, bh, z. K slice (512x64,
// 128KB) + list segment + offsets staged in smem. Warp per query pair,
// 8-lane dot groups, 3 shfl per group-dot.
// ---------------------------------------------------------------------------
__global__ void __launch_bounds__(1024) k_M2(const float* __restrict__ Q,
                                             const float* __restrict__ K) {
    extern __shared__ float ks[];
    float4* ks4 = (float4*)ks;
    int* so = (int*)(ks + SL*Dq);
    int* sl = so + (ZL+1+3);
    int p = blockIdx.x, bh = blockIdx.y, z = blockIdx.z;
    int tid = threadIdx.x, warp = tid >> 5, lane = tid & 31;
    int g = lane >> 3, e = lane & 7;
    int zl0 = z*ZL;

    const float4* Ks = (const float4*)(K + ((size_t)bh*Lq + (size_t)p*SL)*Dq);
    for (int i = tid; i < SL*(Dq/4); i += 1024) ks4[i] = Ks[i];

    int sbeg = g_off[p][zl0];
    int send = g_off[p][zl0 + ZL];
    for (int i = tid; i <= ZL; i += 1024) so[i] = g_off[p][zl0 + i] - sbeg;
    for (int i = tid; i < send - sbeg; i += 1024) sl[i] = g_list[sbeg + i];
    __syncthreads();

    const float4* Q4 = (const float4*)Q;
    int l0 = zl0 + warp;
    #pragma unroll 1
    for (int i = 0; i < 16; i += 2) {
        int la = l0 + 32*i, lb = la + 32;
        int lla = warp + 32*i, llb = lla + 32;
        int a0 = so[lla], a1 = so[lla+1];
        int b0 = so[llb], b1 = so[llb+1];
        size_t qra = ((size_t)bh*Lq + la)*16;
        size_t qrb = ((size_t)bh*Lq + lb)*16;
        float4 qa0 = Q4[qra + e], qa1 = Q4[qra + e + 8];
        float4 qb0 = Q4[qrb + e], qb1 = Q4[qrb + e + 8];
        float mx0 = -INFINITY, sm0 = 0.f, mx1 = -INFINITY, sm1 = 0.f;
        int c0 = a0, c1 = b0;
        while (c0 < a1 || c1 < b1) {
            float pr0 = 0.f, pr1 = 0.f;
            bool v0 = false, v1 = false;
            if (c0 < a1) {
                int idx = c0 + g; v0 = idx < a1;
                int j = sl[v0 ? idx : a0];
                const float4* kb = ks4 + (j << 4);
                float4 x = kb[e], y = kb[e + 8];
                pr0 = qa0.x*x.x + qa0.y*x.y + qa0.z*x.z + qa0.w*x.w
                    + qa1.x*y.x + qa1.y*y.y + qa1.z*y.z + qa1.w*y.w;
            }
            if (c1 < b1) {
                int idx = c1 + g; v1 = idx < b1;
                int j = sl[v1 ? idx : b0];
                const float4* kb = ks4 + (j << 4);
                float4 x = kb[e], y = kb[e + 8];
                pr1 = qb0.x*x.x + qb0.y*x.y + qb0.z*x.z + qb0.w*x.w
                    + qb1.x*y.x + qb1.y*y.y + qb1.z*y.z + qb1.w*y.w;
            }
            pr0 += __shfl_xor_sync(0xffffffffu, pr0, 1);
            pr1 += __shfl_xor_sync(0xffffffffu, pr1, 1);
            pr0 += __shfl_xor_sync(0xffffffffu, pr0, 2);
            pr1 += __shfl_xor_sync(0xffffffffu, pr1, 2);
            pr0 += __shfl_xor_sync(0xffffffffu, pr0, 4);
            pr1 += __shfl_xor_sync(0xffffffffu, pr1, 4);
            if (v0) { mx0 = fmaxf(mx0, pr0); sm0 += pr0; }
            if (v1) { mx1 = fmaxf(mx1, pr1); sm1 += pr1; }
            c0 += 4; c1 += 4;
        }
        mx0 = fmaxf(mx0, __shfl_xor_sync(0xffffffffu, mx0, 8));
        mx0 = fmaxf(mx0, __shfl_xor_sync(0xffffffffu, mx0, 16));
        sm0 += __shfl_xor_sync(0xffffffffu, sm0, 8);
        sm0 += __shfl_xor_sync(0xffffffffu, sm0, 16);
        mx1 = fmaxf(mx1, __shfl_xor_sync(0xffffffffu, mx1, 8));
        mx1 = fmaxf(mx1, __shfl_xor_sync(0xffffffffu, mx1, 16));
        sm1 += __shfl_xor_sync(0xffffffffu, sm1, 8);
        sm1 += __shfl_xor_sync(0xffffffffu, sm1, 16);
        if (lane == 0) {
            g_part2[((size_t)p*BH + bh)*Lq + la] = make_float2(mx0, sm0);
            g_part2[((size_t)p*BH + bh)*Lq + lb] = make_float2(mx1, sm1);
        }
    }
}

// ---------------------------------------------------------------------------
// k_topk: radix-select top-40 (exact threshold, lowest-index tie-break).
// ---------------------------------------------------------------------------
__global__ void k_topk() {
    int bh = blockIdx.x, tid = threadIdx.x;
    __shared__ unsigned keys[Lq];
    __shared__ int hist[256];
    __shared__ int tie[Lq];
    __shared__ int tops[NT];
    __shared__ int s_d, s_acc, s_ngt, s_ntie;

    for (int i = tid; i < Lq; i += 256) {
        float mx = -INFINITY, sm = 0.f;
        #pragma unroll
        for (int p = 0; p < NP; ++p) {
            float2 v = g_part2[((size_t)p*BH + bh)*Lq + i];
            mx = fmaxf(mx, v.x); sm += v.y;
        }
        float m = mx - sm * (1.0f/(float)Lq);
        unsigned u = __float_as_uint(m);
        keys[i] = (u & 0x80000000u) ? ~u : (u | 0x80000000u);
    }
    if (tid == 0) { s_ngt = 0; s_ntie = 0; }
    __syncthreads();

    unsigned prefix = 0; int k = NT;
    #pragma unroll
    for (int level = 3; level >= 0; --level) {
        int sh = level*8;
        hist[tid] = 0;
        __syncthreads();
        unsigned maskAbove = (level==3) ? 0u : (0xFFFFFFFFu << (sh+8));
        for (int i = tid; i < Lq; i += 256) {
            unsigned key = keys[i];
            if ((key & maskAbove) == prefix)
                atomicAdd(&hist[(key >> sh) & 255], 1);
        }
        __syncthreads();
        if (tid == 0) {
            int acc = 0, d = 255;
            for (; d > 0; --d) { if (acc + hist[d] >= k) break; acc += hist[d]; }
            s_d = d; s_acc = acc;
        }
        __syncthreads();
        k -= s_acc;
        prefix |= ((unsigned)s_d) << sh;
        __syncthreads();
    }
    unsigned T = prefix;

    for (int i = tid; i < Lq; i += 256) {
        unsigned key = keys[i];
        if (key > T)       { int pos = atomicAdd(&s_ngt, 1);  tops[pos] = i; }
        else if (key == T) { int pos = atomicAdd(&s_ntie, 1); tie[pos]  = i; }
    }
    __syncthreads();
    int ngt = s_ngt, ntie = s_ntie;
    if (tid < 32) {
        for (int t = 0; t < k; ++t) {
            long long best = 0x7FFFFFFFFFFFFFFFLL;
            for (int i = tid; i < ntie; i += 32) {
                long long c = ((long long)tie[i] << 32) | (unsigned)i;
                if (c < best) best = c;
            }
            #pragma unroll
            for (int o = 16; o; o >>= 1) {
                long long c = __shfl_xor_sync(0xffffffffu, best, o);
                if (c < best) best = c;
            }
            if (tid == 0) {
                int slot = (int)(best & 0xffffffffu);
                tops[ngt + t] = (int)(best >> 32);
                tie[slot] = 0x7FFFFFFF;
            }
            __syncwarp();
        }
    }
    __syncthreads();

    if (tid < NT) {
        g_top[bh*NT + tid] = tops[tid];
        g_sel[bh*Lq + tops[tid]] = tid;
    }
}

// ---------------------------------------------------------------------------
// k_sav: FUSED score+exp+AV per (j-tile 128, bh). 256 threads, ~63KB smem
// -> 2-3 CTAs/SM. Phase A = R8's proven k_score structure but P lands in
// smem (no g_S). Phase B = AV partials from smem P + gmem V.
// ---------------------------------------------------------------------------
__global__ void __launch_bounds__(256) k_sav(const float* __restrict__ Q,
                                             const float* __restrict__ K,
                                             const float* __restrict__ V) {
    extern __shared__ char sm_raw[];
    float*  kt   = (float*)sm_raw;                         // JT*65 floats
    float4* qs4  = (float4*)(sm_raw + JT*65*4);            // NT*16 float4
    float*  P    = (float*)(sm_raw + JT*65*4 + NT*16*16);  // NT*JT floats
    int*    mtop = (int*)  (sm_raw + JT*65*4 + NT*16*16 + NT*JT*4);
    float*  dsum = (float*)(sm_raw + JT*65*4 + NT*16*16 + NT*JT*4 + NT*4);

    int jtx = blockIdx.x, bh = blockIdx.y;
    int jt0 = jtx * JT;
    int tid = threadIdx.x, lane = tid & 31;
    int j = tid & (JT-1), half = tid >> 7;                 // 128 j x 2 u-halves

    if (tid < NT) { mtop[tid] = g_top[bh*NT + tid]; dsum[tid] = 0.f; }
    __syncthreads();

    const float4* Q4 = (const float4*)Q;
    for (int i = tid; i < NT*16; i += 256) {
        int u = i >> 4, d4 = i & 15;
        qs4[i] = Q4[((size_t)bh*Lq + mtop[u])*16 + d4];
    }
    const float4* K4 = (const float4*)K;
    for (int i = tid; i < JT*16; i += 256) {
        int r = i >> 4, c4 = i & 15;
        float4 v = K4[((size_t)bh*Lq + jt0 + r)*16 + c4];
        kt[r*65 + c4*4+0] = v.x; kt[r*65 + c4*4+1] = v.y;
        kt[r*65 + c4*4+2] = v.z; kt[r*65 + c4*4+3] = v.w;
    }
    __syncthreads();

    // ---- Phase A: scores -> exp -> smem P ----
    float kr[Dq];
    #pragma unroll
    for (int d = 0; d < Dq; ++d) kr[d] = kt[j*65 + d];

    int jg = jt0 + j;
    int u0 = half * 20;
    #pragma unroll 1
    for (int u = u0; u < u0 + 20; ++u) {
        int m = mtop[u];
        if (jt0 > m) { P[u*JT + j] = 0.f; continue; }      // block-uniform skip
        float s = 0.f;
        #pragma unroll
        for (int d4 = 0; d4 < 16; ++d4) {
            float4 qv = qs4[u*16 + d4];
            s += kr[d4*4+0]*qv.x + kr[d4*4+1]*qv.y + kr[d4*4+2]*qv.z + kr[d4*4+3]*qv.w;
        }
        float e = (jg > m) ? 0.f : __expf(s * 0.125f);
        P[u*JT + j] = e;
        float v = e;
        v += __shfl_xor_sync(0xffffffffu, v, 1);
        v += __shfl_xor_sync(0xffffffffu, v, 2);
        v += __shfl_xor_sync(0xffffffffu, v, 4);
        v += __shfl_xor_sync(0xffffffffu, v, 8);
        v += __shfl_xor_sync(0xffffffffu, v, 16);
        if (lane == 0) atomicAdd(&dsum[u], v);
    }
    __syncthreads();
    if (tid < NT) atomicAdd(&g_den[bh*NT + tid], dsum[tid]);

    // ---- Phase B: AV partials from smem P ----
    int d = tid & 63, ug = tid >> 6;                       // 4 groups x 10 u
    const float4* P4 = (const float4*)P;                   // row stride 32 f4
    const float* Vb = V + ((size_t)bh*Lq + jt0)*Dq + d;
    float acc[10];
    #pragma unroll
    for (int k = 0; k < 10; ++k) acc[k] = 0.f;

    #pragma unroll 1
    for (int j4 = 0; j4 < JT/4; ++j4) {
        float v0 = Vb[(size_t)(j4*4+0)*Dq], v1 = Vb[(size_t)(j4*4+1)*Dq];
        float v2 = Vb[(size_t)(j4*4+2)*Dq], v3 = Vb[(size_t)(j4*4+3)*Dq];
        #pragma unroll
        for (int k = 0; k < 10; ++k) {
            float4 pv = P4[(ug*10 + k)*(JT/4) + j4];
            acc[k] += pv.x*v0 + pv.y*v1 + pv.z*v2 + pv.w*v3;
        }
    }
    #pragma unroll
    for (int k = 0; k < 10; ++k)
        g_part[(((size_t)bh*NJT + jtx)*NT + ug*10 + k)*Dq + d] = acc[k];
}

// ---------------------------------------------------------------------------
// cumsum: chunk sums, then fused (prefix + scan + combine + scatter).
// ---------------------------------------------------------------------------
__global__ void k_csum1(const float* __restrict__ V) {
    int bh = blockIdx.y;
    int ch = blockIdx.x*4 + (threadIdx.x >> 6);
    int d  = threadIdx.x & 63;
    const float* v = V + ((size_t)bh*Lq + ch*CHLEN)*Dq + d;
    float a = 0.f;
    #pragma unroll
    for (int l = 0; l < CHLEN; l += 4) {
        float x0 = v[(size_t)l*Dq],     x1 = v[(size_t)(l+1)*Dq];
        float x2 = v[(size_t)(l+2)*Dq], x3 = v[(size_t)(l+3)*Dq];
        a += (x0+x1) + (x2+x3);
    }
    g_csum[(bh*NCH + ch)*Dq + d] = a;
}

__global__ void k_csum23(const float* __restrict__ V, float* __restrict__ O) {
    int bh = blockIdx.y;
    int ch = blockIdx.x*4 + (threadIdx.x >> 6);
    int d  = threadIdx.x & 63;

    float a = 0.f;                       // exclusive prefix over chunks < ch
    int c = 0;
    for (; c + 4 <= ch; c += 4) {
        float x0 = g_csum[(bh*NCH + c+0)*Dq + d];
        float x1 = g_csum[(bh*NCH + c+1)*Dq + d];
        float x2 = g_csum[(bh*NCH + c+2)*Dq + d];
        float x3 = g_csum[(bh*NCH + c+3)*Dq + d];
        a += (x0+x1) + (x2+x3);
    }
    for (; c < ch; ++c) a += g_csum[(bh*NCH + c)*Dq + d];

    int l0 = ch*CHLEN;
    size_t base = ((size_t)bh*Lq + l0)*Dq + d;
    const int* sel = g_sel + bh*Lq + l0;
    #pragma unroll 4
    for (int l = 0; l < CHLEN; ++l) {
        a += V[base + (size_t)l*Dq];
        float out = a;
        int s = sel[l];
        if (s >= 0) {
            float acc16 = 0.f;
            #pragma unroll
            for (int js = 0; js < NJT; ++js)
                acc16 += g_part[(((size_t)bh*NJT + js)*NT + s)*Dq + d];
            out = acc16 / g_den[bh*NT + s];
        }
        O[base + (size_t)l*Dq] = out;
    }
}

extern "C" void kernel_launch(void* const* d_in, const int* in_sizes, int n_in,
                              void* d_out, int out_size) {
    const float* Q = (const float*)d_in[0];
    const float* K = (const float*)d_in[1];
    const float* V = (const float*)d_in[2];
    const int*   I = (const int*)  d_in[3];
    float* O = (float*)d_out;

    cudaFuncSetAttribute(k_M2,  cudaFuncAttributeMaxDynamicSharedMemorySize, SMEM_M2);
    cudaFuncSetAttribute(k_sav, cudaFuncAttributeMaxDynamicSharedMemorySize, SMEM_SAV);

    k_cnt   <<<Lq/256, 256>>>(I);
    k_scan  <<<1, 256>>>();
    k_fill  <<<Lq/256, 256>>>(I);
    k_M2    <<<dim3(NP, BH, ZSP), 1024, SMEM_M2>>>(Q, K);
    k_topk  <<<BH, 256>>>();
    k_sav   <<<dim3(NJT, BH), 256, SMEM_SAV>>>(Q, K, V);
    k_csum1 <<<dim3(NCH/4, BH), 256>>>(V);
    k_csum23<<<dim3(NCH/4, BH), 256>>>(V, O);
}

// round 12
// speedup vs baseline: 1.2809x; 1.0829x over previous
#include <cuda_runtime.h>
#include <math.h>

// B,H,L,D = 4,8,2048,64 ; FACTOR=5 -> sample_k = n_top = 40
#define Bq    4
#define Hq    8
#define Lq    2048
#define Dq    64
#define BH    (Bq*Hq)
#define SK    40
#define NT    40
#define NP    4            // K slices for k_M2
#define SL    (Lq/NP)      // 512 rows per slice
#define ZSP   4            // l-splits per (p,bh) in k_M2
#define ZL    (Lq/ZSP)     // 512 queries per z
#define LMAX  (ZL*SK)      // staged list worst case
#define NCH   64           // cumsum chunks
#define CHLEN (Lq/NCH)     // 32
#define NJT   16           // j-tiles (of 128) for fused score+AV
#define JT    (Lq/NJT)     // 128
#define SMEM_M2  (SL*Dq*4 + (ZL+1+3)*4 + LMAX*4)
// sav smem offsets (bytes): qs4 | kt | P | Vs | mtop | dsum | ucnt
#define SAV_QS   0
#define SAV_KT   (SAV_QS + NT*16*16)        // 10240
#define SAV_P    (SAV_KT + JT*65*4)         // 43520
#define SAV_VS   (SAV_P  + NT*JT*4)         // 64000
#define SAV_MT   (SAV_VS + JT*Dq*4)         // 96768
#define SAV_DS   (SAV_MT + NT*4)            // 96928
#define SAV_UC   (SAV_DS + NT*4)            // 97088
#define SMEM_SAV (SAV_UC + 64)

// ---- device scratch (no allocations allowed) ----
__device__ int    g_cnt[NP][Lq];
__device__ int    g_off[NP][Lq+1];     // per-slice offsets (zero-based)
__device__ int    g_list[NP][Lq*SK];   // per-slice sample lists
__device__ float2 g_part2[NP*BH*Lq];
__device__ int    g_top[BH*NT];        // sorted desc by row index
__device__ float  g_den[BH*NT];
__device__ float  g_part[BH*NJT*NT*Dq];
__device__ float  g_csum[BH*NCH*Dq];

// ---------------------------------------------------------------------------
// Prep 1: per-query per-slice counts; zero g_den.
// ---------------------------------------------------------------------------
__global__ void k_cnt(const int* __restrict__ I) {
    int l = blockIdx.x*256 + threadIdx.x;          // grid 8
    if (l < BH*NT) g_den[l] = 0.f;
    int c0=0,c1=0,c2=0,c3=0;
    const int* r = I + l*SK;
    #pragma unroll
    for (int s = 0; s < SK; ++s) {
        int p = r[s] >> 9;
        c0 += (p==0); c1 += (p==1); c2 += (p==2); c3 += (p==3);
    }
    g_cnt[0][l]=c0; g_cnt[1][l]=c1; g_cnt[2][l]=c2; g_cnt[3][l]=c3;
}

// Prep 2: per-slice exclusive prefix (grid NP, zero-based per slice)
__global__ void k_scan() {
    __shared__ int wsum[8];
    int p = blockIdx.x;
    int tid = threadIdx.x, lane = tid & 31, wid = tid >> 5;
    int loc[8]; int s = 0;
    #pragma unroll
    for (int k = 0; k < 8; ++k) { loc[k] = s; s += g_cnt[p][tid*8+k]; }
    int v = s;
    #pragma unroll
    for (int o = 1; o < 32; o <<= 1) {
        int t = __shfl_up_sync(0xffffffffu, v, o);
        if (lane >= o) v += t;
    }
    if (lane == 31) wsum[wid] = v;
    __syncthreads();
    if (tid == 0) {
        int a = 0;
        #pragma unroll
        for (int i = 0; i < 8; ++i) { int t = wsum[i]; wsum[i] = a; a += t; }
    }
    __syncthreads();
    int excl = v - s + wsum[wid];
    #pragma unroll
    for (int k = 0; k < 8; ++k) g_off[p][tid*8+k] = excl + loc[k];
    if (tid == 255) g_off[p][Lq] = excl + s;
}

// Prep 3: fill per-slice lists (local row index within slice)
__global__ void k_fill(const int* __restrict__ I) {
    int l = blockIdx.x*256 + threadIdx.x;
    int o0=g_off[0][l], o1=g_off[1][l], o2=g_off[2][l], o3=g_off[3][l];
    const int* r = I + l*SK;
    #pragma unroll
    for (int s = 0; s < SK; ++s) {
        int j = r[s];
        int p = j >> 9, jj = j & (SL-1);
        if      (p==0) g_list[0][o0++] = jj;
        else if (p==1) g_list[1][o1++] = jj;
        else if (p==2) g_list[2][o2++] = jj;
        else           g_list[3][o3++] = jj;
    }
}

// ---------------------------------------------------------------------------
// k_M2: proven R7 config + csum1 epilogue on the first 128 blocks (their
// DRAM reads overlap remaining M2 compute waves).
// ---------------------------------------------------------------------------
__global__ void __launch_bounds__(1024) k_M2(const float* __restrict__ Q,
                                             const float* __restrict__ K,
                                             const float* __restrict__ V) {
    extern __shared__ float ks[];
    float4* ks4 = (float4*)ks;
    int* so = (int*)(ks + SL*Dq);
    int* sl = so + (ZL+1+3);
    int p = blockIdx.x, bh = blockIdx.y, z = blockIdx.z;
    int tid = threadIdx.x, warp = tid >> 5, lane = tid & 31;
    int g = lane >> 3, e = lane & 7;
    int zl0 = z*ZL;

    const float4* Ks = (const float4*)(K + ((size_t)bh*Lq + (size_t)p*SL)*Dq);
    for (int i = tid; i < SL*(Dq/4); i += 1024) ks4[i] = Ks[i];

    int sbeg = g_off[p][zl0];
    int send = g_off[p][zl0 + ZL];
    for (int i = tid; i <= ZL; i += 1024) so[i] = g_off[p][zl0 + i] - sbeg;
    for (int i = tid; i < send - sbeg; i += 1024) sl[i] = g_list[p][sbeg + i];
    __syncthreads();

    const float4* Q4 = (const float4*)Q;
    int l0 = zl0 + warp;
    #pragma unroll 1
    for (int i = 0; i < 16; i += 2) {
        int la = l0 + 32*i, lb = la + 32;
        int lla = warp + 32*i, llb = lla + 32;
        int a0 = so[lla], a1 = so[lla+1];
        int b0 = so[llb], b1 = so[llb+1];
        size_t qra = ((size_t)bh*Lq + la)*16;
        size_t qrb = ((size_t)bh*Lq + lb)*16;
        float4 qa0 = Q4[qra + e], qa1 = Q4[qra + e + 8];
        float4 qb0 = Q4[qrb + e], qb1 = Q4[qrb + e + 8];
        float mx0 = -INFINITY, sm0 = 0.f, mx1 = -INFINITY, sm1 = 0.f;
        int c0 = a0, c1 = b0;
        while (c0 < a1 || c1 < b1) {
            float pr0 = 0.f, pr1 = 0.f;
            bool v0 = false, v1 = false;
            if (c0 < a1) {
                int idx = c0 + g; v0 = idx < a1;
                int j = sl[v0 ? idx : a0];
                const float4* kb = ks4 + (j << 4);
                float4 x = kb[e], y = kb[e + 8];
                pr0 = qa0.x*x.x + qa0.y*x.y + qa0.z*x.z + qa0.w*x.w
                    + qa1.x*y.x + qa1.y*y.y + qa1.z*y.z + qa1.w*y.w;
            }
            if (c1 < b1) {
                int idx = c1 + g; v1 = idx < b1;
                int j = sl[v1 ? idx : b0];
                const float4* kb = ks4 + (j << 4);
                float4 x = kb[e], y = kb[e + 8];
                pr1 = qb0.x*x.x + qb0.y*x.y + qb0.z*x.z + qb0.w*x.w
                    + qb1.x*y.x + qb1.y*y.y + qb1.z*y.z + qb1.w*y.w;
            }
            pr0 += __shfl_xor_sync(0xffffffffu, pr0, 1);
            pr1 += __shfl_xor_sync(0xffffffffu, pr1, 1);
            pr0 += __shfl_xor_sync(0xffffffffu, pr0, 2);
            pr1 += __shfl_xor_sync(0xffffffffu, pr1, 2);
            pr0 += __shfl_xor_sync(0xffffffffu, pr0, 4);
            pr1 += __shfl_xor_sync(0xffffffffu, pr1, 4);
            if (v0) { mx0 = fmaxf(mx0, pr0); sm0 += pr0; }
            if (v1) { mx1 = fmaxf(mx1, pr1); sm1 += pr1; }
            c0 += 4; c1 += 4;
        }
        mx0 = fmaxf(mx0, __shfl_xor_sync(0xffffffffu, mx0, 8));
        mx0 = fmaxf(mx0, __shfl_xor_sync(0xffffffffu, mx0, 16));
        sm0 += __shfl_xor_sync(0xffffffffu, sm0, 8);
        sm0 += __shfl_xor_sync(0xffffffffu, sm0, 16);
        mx1 = fmaxf(mx1, __shfl_xor_sync(0xffffffffu, mx1, 8));
        mx1 = fmaxf(mx1, __shfl_xor_sync(0xffffffffu, mx1, 16));
        sm1 += __shfl_xor_sync(0xffffffffu, sm1, 8);
        sm1 += __shfl_xor_sync(0xffffffffu, sm1, 16);
        if (lane == 0) {
            g_part2[((size_t)p*BH + bh)*Lq + la] = make_float2(mx0, sm0);
            g_part2[((size_t)p*BH + bh)*Lq + lb] = make_float2(mx1, sm1);
        }
    }

    // ---- csum1 epilogue: first 128 blocks compute V chunk sums ----
    int mbid = blockIdx.x + NP*blockIdx.y + NP*BH*blockIdx.z;
    if (mbid < (NCH*BH)/16) {
        int gcid = mbid*16 + (tid >> 6);
        int d = tid & 63;
        int cbh = gcid >> 6, ch = gcid & (NCH-1);
        const float* v = V + ((size_t)cbh*Lq + ch*CHLEN)*Dq + d;
        float a = 0.f;
        #pragma unroll
        for (int l = 0; l < CHLEN; l += 4) {
            float x0 = v[(size_t)l*Dq],     x1 = v[(size_t)(l+1)*Dq];
            float x2 = v[(size_t)(l+2)*Dq], x3 = v[(size_t)(l+3)*Dq];
            a += (x0+x1) + (x2+x3);
        }
        g_csum[(cbh*NCH + ch)*Dq + d] = a;
    }
}

// ---------------------------------------------------------------------------
// k_topk: radix-select top-40 (exact threshold, lowest-index tie-break),
// then rank-sort by row index DESC (makes live-u sets prefix-shaped in k_sav).
// ---------------------------------------------------------------------------
__global__ void k_topk() {
    int bh = blockIdx.x, tid = threadIdx.x;
    __shared__ unsigned keys[Lq];
    __shared__ int hist[256];
    __shared__ int tie[Lq];
    __shared__ int tops[NT];
    __shared__ int sorted[NT];
    __shared__ int s_d, s_acc, s_ngt, s_ntie;

    for (int i = tid; i < Lq; i += 256) {
        float mx = -INFINITY, sm = 0.f;
        #pragma unroll
        for (int p = 0; p < NP; ++p) {
            float2 v = g_part2[((size_t)p*BH + bh)*Lq + i];
            mx = fmaxf(mx, v.x); sm += v.y;
        }
        float m = mx - sm * (1.0f/(float)Lq);
        unsigned u = __float_as_uint(m);
        keys[i] = (u & 0x80000000u) ? ~u : (u | 0x80000000u);
    }
    if (tid == 0) { s_ngt = 0; s_ntie = 0; }
    __syncthreads();

    unsigned prefix = 0; int k = NT;
    #pragma unroll
    for (int level = 3; level >= 0; --level) {
        int sh = level*8;
        hist[tid] = 0;
        __syncthreads();
        unsigned maskAbove = (level==3) ? 0u : (0xFFFFFFFFu << (sh+8));
        for (int i = tid; i < Lq; i += 256) {
            unsigned key = keys[i];
            if ((key & maskAbove) == prefix)
                atomicAdd(&hist[(key >> sh) & 255], 1);
        }
        __syncthreads();
        if (tid == 0) {
            int acc = 0, d = 255;
            for (; d > 0; --d) { if (acc + hist[d] >= k) break; acc += hist[d]; }
            s_d = d; s_acc = acc;
        }
        __syncthreads();
        k -= s_acc;
        prefix |= ((unsigned)s_d) << sh;
        __syncthreads();
    }
    unsigned T = prefix;

    for (int i = tid; i < Lq; i += 256) {
        unsigned key = keys[i];
        if (key > T)       { int pos = atomicAdd(&s_ngt, 1);  tops[pos] = i; }
        else if (key == T) { int pos = atomicAdd(&s_ntie, 1); tie[pos]  = i; }
    }
    __syncthreads();
    int ngt = s_ngt, ntie = s_ntie;
    if (tid < 32) {
        for (int t = 0; t < k; ++t) {
            long long best = 0x7FFFFFFFFFFFFFFFLL;
            for (int i = tid; i < ntie; i += 32) {
                long long c = ((long long)tie[i] << 32) | (unsigned)i;
                if (c < best) best = c;
            }
            #pragma unroll
            for (int o = 16; o; o >>= 1) {
                long long c = __shfl_xor_sync(0xffffffffu, best, o);
                if (c < best) best = c;
            }
            if (tid == 0) {
                int slot = (int)(best & 0xffffffffu);
                tops[ngt + t] = (int)(best >> 32);
                tie[slot] = 0x7FFFFFFF;
            }
            __syncwarp();
        }
    }
    __syncthreads();

    // rank-sort desc by row index (rows distinct -> unique ranks)
    if (tid < NT) {
        int me = tops[tid], r = 0;
        #pragma unroll
        for (int jj = 0; jj < NT; ++jj) r += (tops[jj] > me);
        sorted[r] = me;
    }
    __syncthreads();
    if (tid < NT) g_top[bh*NT + tid] = sorted[tid];
}

// ---------------------------------------------------------------------------
// k_sav: fused score+exp+AV per (j-tile 128, bh), V staged in smem, live-u
// prefix bounds (g_top sorted desc). Epilogue: cumsum output for one
// chunk-group (csum23 without the scatter; k_fix patches selected rows).
// ---------------------------------------------------------------------------
__global__ void __launch_bounds__(256) k_sav(const float* __restrict__ Q,
                                             const float* __restrict__ K,
                                             const float* __restrict__ V,
                                             float* __restrict__ O) {
    extern __shared__ char sm_raw[];
    float4* qs4  = (float4*)(sm_raw + SAV_QS);
    float*  kt   = (float*) (sm_raw + SAV_KT);
    float*  P    = (float*) (sm_raw + SAV_P);
    float*  Vs   = (float*) (sm_raw + SAV_VS);
    int*    mtop = (int*)   (sm_raw + SAV_MT);
    float*  dsum = (float*) (sm_raw + SAV_DS);
    int*    puc  = (int*)   (sm_raw + SAV_UC);

    int jtx = blockIdx.x, bh = blockIdx.y;
    int jt0 = jtx * JT;
    int tid = threadIdx.x, lane = tid & 31;
    int j = tid & (JT-1), half = tid >> 7;

    if (tid < NT) { mtop[tid] = g_top[bh*NT + tid]; dsum[tid] = 0.f; }
    __syncthreads();
    if (tid == 0) {
        int c = 0;
        while (c < NT && mtop[c] >= jt0) ++c;
        *puc = c;
    }

    const float4* Q4 = (const float4*)Q;
    for (int i = tid; i < NT*16; i += 256) {
        int u = i >> 4, d4 = i & 15;
        qs4[i] = Q4[((size_t)bh*Lq + mtop[u])*16 + d4];
    }
    const float4* K4 = (const float4*)K;
    for (int i = tid; i < JT*16; i += 256) {
        int r = i >> 4, c4 = i & 15;
        float4 v = K4[((size_t)bh*Lq + jt0 + r)*16 + c4];
        kt[r*65 + c4*4+0] = v.x; kt[r*65 + c4*4+1] = v.y;
        kt[r*65 + c4*4+2] = v.z; kt[r*65 + c4*4+3] = v.w;
    }
    const float4* V4 = (const float4*)V;
    float4* Vs4 = (float4*)Vs;
    for (int i = tid; i < JT*16; i += 256)
        Vs4[i] = V4[((size_t)bh*Lq + jt0)*16 + i];
    __syncthreads();
    int ucnt = *puc;

    // ---- Phase A: scores -> exp -> smem P (live u only) ----
    float kr[Dq];
    #pragma unroll
    for (int d = 0; d < Dq; ++d) kr[d] = kt[j*65 + d];

    int jg = jt0 + j;
    #pragma unroll 1
    for (int u = half; u < ucnt; u += 2) {
        int m = mtop[u];
        float s = 0.f;
        #pragma unroll
        for (int d4 = 0; d4 < 16; ++d4) {
            float4 qv = qs4[u*16 + d4];
            s += kr[d4*4+0]*qv.x + kr[d4*4+1]*qv.y + kr[d4*4+2]*qv.z + kr[d4*4+3]*qv.w;
        }
        float e = (jg > m) ? 0.f : __expf(s * 0.125f);
        P[u*JT + j] = e;
        float v = e;
        v += __shfl_xor_sync(0xffffffffu, v, 1);
        v += __shfl_xor_sync(0xffffffffu, v, 2);
        v += __shfl_xor_sync(0xffffffffu, v, 4);
        v += __shfl_xor_sync(0xffffffffu, v, 8);
        v += __shfl_xor_sync(0xffffffffu, v, 16);
        if (lane == 0) atomicAdd(&dsum[u], v);
    }
    __syncthreads();
    if (tid < NT) atomicAdd(&g_den[bh*NT + tid], dsum[tid]);

    // ---- Phase B: AV partials from smem P + smem V ----
    int d = tid & 63, ug = tid >> 6;
    const float4* P4 = (const float4*)P;
    float acc[10];
    #pragma unroll
    for (int k = 0; k < 10; ++k) acc[k] = 0.f;

    #pragma unroll 1
    for (int j4 = 0; j4 < JT/4; ++j4) {
        float v0 = Vs[(j4*4+0)*Dq + d], v1 = Vs[(j4*4+1)*Dq + d];
        float v2 = Vs[(j4*4+2)*Dq + d], v3 = Vs[(j4*4+3)*Dq + d];
        #pragma unroll
        for (int k = 0; k < 10; ++k) {
            int u = ug*10 + k;
            if (u < ucnt) {
                float4 pv = P4[u*(JT/4) + j4];
                acc[k] += pv.x*v0 + pv.y*v1 + pv.z*v2 + pv.w*v3;
            }
        }
    }
    #pragma unroll
    for (int k = 0; k < 10; ++k)
        g_part[(((size_t)bh*NJT + jtx)*NT + ug*10 + k)*Dq + d] = acc[k];

    // ---- Epilogue: cumsum output for one chunk-group (no scatter) ----
    {
        int sbid = jtx + NJT*bh;                 // [0, 512)
        int cbh = sbid >> 4;
        int ch = (sbid & 15)*4 + (tid >> 6);
        int dd = tid & 63;
        float a = 0.f;
        int c = 0;
        for (; c + 4 <= ch; c += 4) {
            float x0 = g_csum[(cbh*NCH + c+0)*Dq + dd];
            float x1 = g_csum[(cbh*NCH + c+1)*Dq + dd];
            float x2 = g_csum[(cbh*NCH + c+2)*Dq + dd];
            float x3 = g_csum[(cbh*NCH + c+3)*Dq + dd];
            a += (x0+x1) + (x2+x3);
        }
        for (; c < ch; ++c) a += g_csum[(cbh*NCH + c)*Dq + dd];

        size_t base = ((size_t)cbh*Lq + ch*CHLEN)*Dq + dd;
        #pragma unroll 4
        for (int l = 0; l < CHLEN; ++l) {
            a += V[base + (size_t)l*Dq];
            O[base + (size_t)l*Dq] = a;
        }
    }
}

// ---------------------------------------------------------------------------
// k_fix: overwrite the 40 selected rows per bh with normalized attention.
// ---------------------------------------------------------------------------
__global__ void k_fix(float* __restrict__ O) {
    int bh = blockIdx.x, tid = threadIdx.x;
    for (int i = tid; i < NT*Dq; i += 256) {
        int u = i >> 6, d = i & 63;
        int row = g_top[bh*NT + u];
        float acc = 0.f;
        #pragma unroll
        for (int js = 0; js < NJT; ++js)
            acc += g_part[(((size_t)bh*NJT + js)*NT + u)*Dq + d];
        O[((size_t)bh*Lq + row)*Dq + d] = acc / g_den[bh*NT + u];
    }
}

extern "C" void kernel_launch(void* const* d_in, const int* in_sizes, int n_in,
                              void* d_out, int out_size) {
    const float* Q = (const float*)d_in[0];
    const float* K = (const float*)d_in[1];
    const float* V = (const float*)d_in[2];
    const int*   I = (const int*)  d_in[3];
    float* O = (float*)d_out;

    cudaFuncSetAttribute(k_M2,  cudaFuncAttributeMaxDynamicSharedMemorySize, SMEM_M2);
    cudaFuncSetAttribute(k_sav, cudaFuncAttributeMaxDynamicSharedMemorySize, SMEM_SAV);

    k_cnt  <<<Lq/256, 256>>>(I);
    k_scan <<<NP, 256>>>();
    k_fill <<<Lq/256, 256>>>(I);
    k_M2   <<<dim3(NP, BH, ZSP), 1024, SMEM_M2>>>(Q, K, V);
    k_topk <<<BH, 256>>>();
    k_sav  <<<dim3(NJT, BH), 256, SMEM_SAV>>>(Q, K, V, O);
    k_fix  <<<BH, 256>>>(O);
}